// round 1
// baseline (speedup 1.0000x reference)
#include <cuda_runtime.h>
#include <math.h>

// ---------------- problem constants ----------------
#define BB 32
#define SS 512
#define DM 512
#define NH 8
#define DK 64
#define DINNER 2048
#define MTOT (BB * SS)              // 16384 rows
#define ENC_ELEMS (BB * SS * DM)    // 8388608
#define EPSLN 1e-3f

// ---------------- scratch (device globals; no allocation allowed) ----------------
__device__ float g_xc[MTOT * DM];        // compacted input      33.5 MB
__device__ float g_q[MTOT * DM];         // [b,s,h,k]            33.5 MB
__device__ float g_k[MTOT * DM];
__device__ float g_v[MTOT * DM];
__device__ float g_heads[MTOT * DM];     // attn heads concat
__device__ float g_tmp[MTOT * DM];       // pre-LN gemm out (reused)
__device__ float g_attnout[MTOT * DM];   // LN1 output
__device__ float g_ffnh[MTOT * DINNER];  // FFN hidden          134 MB
__device__ float g_wq[DM * DM];          // packed [d, h*64+k]
__device__ float g_wk[DM * DM];
__device__ float g_wv[DM * DM];
__device__ int   g_idx[BB * SS];
__device__ int   g_nkeep[BB];

// ---------------- skipper: stable compaction scan ----------------
__global__ void skipper_scan(const int* __restrict__ keep, int* __restrict__ idx,
                             int* __restrict__ nkeep) {
    int b = blockIdx.x, t = threadIdx.x;  // 512 threads
    __shared__ int sh[SS];
    int v = keep[b * SS + t] > 0;
    sh[t] = v;
    __syncthreads();
    for (int off = 1; off < SS; off <<= 1) {
        int x = (t >= off) ? sh[t - off] : 0;
        __syncthreads();
        sh[t] += x;
        __syncthreads();
    }
    int incl = sh[t];
    if (v) idx[b * SS + incl - 1] = t;
    if (t == SS - 1) nkeep[b] = incl;
}

// gather compacted rows, zero the tail
__global__ void gather_kernel(const float* __restrict__ x, const int* __restrict__ idx,
                              const int* __restrict__ nkeep, float* __restrict__ xc) {
    int bs = blockIdx.x;
    int b = bs >> 9, s = bs & 511;
    int nk = nkeep[b];
    float4* o = (float4*)(xc + (size_t)bs * DM);
    if (s < nk) {
        const float4* src = (const float4*)(x + ((size_t)b * SS + idx[b * SS + s]) * DM);
        o[threadIdx.x] = src[threadIdx.x];  // 128 thr * 4 = 512
    } else {
        o[threadIdx.x] = make_float4(0.f, 0.f, 0.f, 0.f);
    }
}

// pack per-head weight [H, D, 64] -> [D, H*64]
__global__ void pack_w(const float* __restrict__ w, float* __restrict__ wp) {
    int i = blockIdx.x * 256 + threadIdx.x;  // over 512*512
    int d = i >> 9;
    int n = i & 511;
    int h = n >> 6, kk = n & 63;
    wp[i] = w[(h * DM + d) * DK + kk];
}

// ---------------- classic fp32 SGEMM 128x128x8, 8x8 per thread ----------------
// C[M,N] = A[M,K] @ B[K,N] (+bias per-col, optional relu). M%128==0, N%128==0, K%8==0.
__global__ void __launch_bounds__(256) sgemm_kernel(
    const float* __restrict__ A, const float* __restrict__ B, float* __restrict__ C,
    int M, int N, int K, const float* __restrict__ bias, int relu) {
    __shared__ float As[8][128];
    __shared__ float Bs[8][128];
    int tid = threadIdx.x;
    int brow = blockIdx.y * 128, bcol = blockIdx.x * 128;
    int arow = tid >> 1;             // 0..127
    int acol = (tid & 1) * 4;        // 0 or 4
    int brl = tid >> 5;              // 0..7
    int bcl = (tid & 31) * 4;        // 0..124
    int tx = tid & 15, ty = tid >> 4;
    float acc[8][8];
#pragma unroll
    for (int i = 0; i < 8; i++)
#pragma unroll
        for (int j = 0; j < 8; j++) acc[i][j] = 0.f;

    const float* Ap = A + (size_t)(brow + arow) * K + acol;
    const float* Bp = B + (size_t)brl * N + bcol + bcl;
    for (int k0 = 0; k0 < K; k0 += 8) {
        float4 a4 = *(const float4*)(Ap + k0);
        As[acol + 0][arow] = a4.x;
        As[acol + 1][arow] = a4.y;
        As[acol + 2][arow] = a4.z;
        As[acol + 3][arow] = a4.w;
        float4 b4 = *(const float4*)(Bp + (size_t)k0 * N);
        *(float4*)(&Bs[brl][bcl]) = b4;
        __syncthreads();
#pragma unroll
        for (int kk = 0; kk < 8; kk++) {
            float ar[8], br[8];
#pragma unroll
            for (int i = 0; i < 8; i++) ar[i] = As[kk][ty * 8 + i];
#pragma unroll
            for (int j = 0; j < 8; j++) br[j] = Bs[kk][tx * 8 + j];
#pragma unroll
            for (int i = 0; i < 8; i++)
#pragma unroll
                for (int j = 0; j < 8; j++) acc[i][j] += ar[i] * br[j];
        }
        __syncthreads();
    }
#pragma unroll
    for (int i = 0; i < 8; i++) {
        int r = brow + ty * 8 + i;
#pragma unroll
        for (int j = 0; j < 8; j++) {
            int c = bcol + tx * 8 + j;
            float v = acc[i][j];
            if (bias) v += bias[c];
            if (relu) v = fmaxf(v, 0.f);
            C[(size_t)r * N + c] = v;
        }
    }
}

// ---------------- fused attention: scores -> softmax -> write P -> P@V ----------------
// block: (b,h) x 32-row tile of s.  256 threads. q/k/v layout [b,s,h*64+k].
__global__ void __launch_bounds__(256) attention_kernel(
    const float* __restrict__ q, const float* __restrict__ k, const float* __restrict__ v,
    const int* __restrict__ nkeep, float* __restrict__ attns, float* __restrict__ heads) {
    extern __shared__ float sm[];
    float* Ss = sm;                 // 32*512
    float* Ks = sm + 32 * 512;      // 64*65 (reused for V)
    float* Qs = Ks + 64 * 65;       // 32*65
    int bh = blockIdx.x;
    int b = bh >> 3, h = bh & 7;
    int s0 = blockIdx.y * 32;
    int tid = threadIdx.x;
    int nk = nkeep[b];
    const float inv_temp = 0.04419417382415922f;  // 1/sqrt(512)

    for (int i = tid; i < 32 * 64; i += 256) {
        int r = i >> 6, kk = i & 63;
        Qs[r * 65 + kk] = q[((size_t)(b * SS + s0 + r)) * DM + h * 64 + kk];
    }
    int r = tid >> 3, cg = tid & 7;

    for (int t0 = 0; t0 < SS; t0 += 64) {
        __syncthreads();
        for (int i = tid; i < 64 * 64; i += 256) {
            int tt = i >> 6, kk = i & 63;
            Ks[tt * 65 + kk] = k[((size_t)(b * SS + t0 + tt)) * DM + h * 64 + kk];
        }
        __syncthreads();
        float acc[8];
#pragma unroll
        for (int j = 0; j < 8; j++) acc[j] = 0.f;
#pragma unroll
        for (int kk = 0; kk < 64; kk++) {
            float a = Qs[r * 65 + kk];
#pragma unroll
            for (int j = 0; j < 8; j++) acc[j] += a * Ks[(cg * 8 + j) * 65 + kk];
        }
#pragma unroll
        for (int j = 0; j < 8; j++) {
            int t = t0 + cg * 8 + j;
            Ss[r * 512 + t] = (t < nk) ? acc[j] * inv_temp : -INFINITY;
        }
    }
    __syncthreads();

    // softmax: 8 threads per row; thread owns 64 contiguous cols
    {
        float m = -INFINITY;
        for (int i = 0; i < 64; i++) m = fmaxf(m, Ss[r * 512 + cg * 64 + i]);
        for (int o = 1; o < 8; o <<= 1) m = fmaxf(m, __shfl_xor_sync(~0u, m, o));
        float sum = 0.f;
        for (int i = 0; i < 64; i++) {
            float e = __expf(Ss[r * 512 + cg * 64 + i] - m);
            Ss[r * 512 + cg * 64 + i] = e;
            sum += e;
        }
        for (int o = 1; o < 8; o <<= 1) sum += __shfl_xor_sync(~0u, sum, o);
        float inv = 1.f / sum;
        for (int i = 0; i < 64; i++) Ss[r * 512 + cg * 64 + i] *= inv;
    }
    __syncthreads();

    // write P to attns region: index [h*B + b][s][t]
    {
        float* dst = attns + (((size_t)(h * BB + b)) * SS + s0) * SS;
        for (int i = tid; i < 32 * 512; i += 256) dst[i] = Ss[i];
    }

    // O = P @ V
    float o[8];
#pragma unroll
    for (int j = 0; j < 8; j++) o[j] = 0.f;
    for (int t0 = 0; t0 < SS; t0 += 64) {
        __syncthreads();
        for (int i = tid; i < 64 * 64; i += 256) {
            int tt = i >> 6, vv = i & 63;
            Ks[tt * 65 + vv] = v[((size_t)(b * SS + t0 + tt)) * DM + h * 64 + vv];
        }
        __syncthreads();
#pragma unroll
        for (int tt = 0; tt < 64; tt++) {
            float p = Ss[r * 512 + t0 + tt];
#pragma unroll
            for (int j = 0; j < 8; j++) o[j] += p * Ks[tt * 65 + cg * 8 + j];
        }
    }
#pragma unroll
    for (int j = 0; j < 8; j++)
        heads[((size_t)(b * SS + s0 + r)) * DM + h * 64 + cg * 8 + j] = o[j];
}

// ---------------- layernorm (unbiased var, eps added to std) with residual ----------------
__global__ void ln_kernel(const float* __restrict__ y, const float* __restrict__ resid,
                          const float* __restrict__ g, const float* __restrict__ be,
                          float* __restrict__ out) {
    int row = blockIdx.x;
    int tid = threadIdx.x;  // 128
    float4 a = ((const float4*)(y + (size_t)row * DM))[tid];
    float4 b = ((const float4*)(resid + (size_t)row * DM))[tid];
    float v0 = a.x + b.x, v1 = a.y + b.y, v2 = a.z + b.z, v3 = a.w + b.w;
    float s = v0 + v1 + v2 + v3;
    float ss = v0 * v0 + v1 * v1 + v2 * v2 + v3 * v3;
    for (int o = 16; o; o >>= 1) {
        s += __shfl_xor_sync(~0u, s, o);
        ss += __shfl_xor_sync(~0u, ss, o);
    }
    __shared__ float shs[4], shss[4];
    int w = tid >> 5, l = tid & 31;
    if (l == 0) { shs[w] = s; shss[w] = ss; }
    __syncthreads();
    s = shs[0] + shs[1] + shs[2] + shs[3];
    ss = shss[0] + shss[1] + shss[2] + shss[3];
    float mu = s * (1.f / 512.f);
    float var = fmaxf((ss - 512.f * mu * mu) * (1.f / 511.f), 0.f);
    float inv = 1.f / (sqrtf(var) + EPSLN);
    float4 gg = ((const float4*)g)[tid];
    float4 bb = ((const float4*)be)[tid];
    float4 o;
    o.x = (v0 - mu) * inv * gg.x + bb.x;
    o.y = (v1 - mu) * inv * gg.y + bb.y;
    o.z = (v2 - mu) * inv * gg.z + bb.z;
    o.w = (v3 - mu) * inv * gg.w + bb.w;
    ((float4*)(out + (size_t)row * DM))[tid] = o;
}

// ---------------- launch ----------------
extern "C" void kernel_launch(void* const* d_in, const int* in_sizes, int n_in,
                              void* d_out, int out_size) {
    const float* x      = (const float*)d_in[0];
    const float* w_qs   = (const float*)d_in[1];
    const float* w_ks   = (const float*)d_in[2];
    const float* w_vs   = (const float*)d_in[3];
    const float* proj_w = (const float*)d_in[4];
    const float* proj_b = (const float*)d_in[5];
    const float* ln1_g  = (const float*)d_in[6];
    const float* ln1_b  = (const float*)d_in[7];
    const float* ffn_w1 = (const float*)d_in[8];
    const float* ffn_b1 = (const float*)d_in[9];
    const float* ffn_w2 = (const float*)d_in[10];
    const float* ffn_b2 = (const float*)d_in[11];
    const float* ln2_g  = (const float*)d_in[12];
    const float* ln2_b  = (const float*)d_in[13];
    const int*   keepm  = (const int*)d_in[14];

    float* out = (float*)d_out;
    float* enc_out = out;                 // [B,S,D]
    float* attns   = out + ENC_ELEMS;     // [H*B,S,S]

    float *xc, *q, *k, *v, *heads, *tmp, *attn_out, *ffnh, *wq, *wk, *wv;
    int *idx, *nk;
    cudaGetSymbolAddress((void**)&xc, g_xc);
    cudaGetSymbolAddress((void**)&q, g_q);
    cudaGetSymbolAddress((void**)&k, g_k);
    cudaGetSymbolAddress((void**)&v, g_v);
    cudaGetSymbolAddress((void**)&heads, g_heads);
    cudaGetSymbolAddress((void**)&tmp, g_tmp);
    cudaGetSymbolAddress((void**)&attn_out, g_attnout);
    cudaGetSymbolAddress((void**)&ffnh, g_ffnh);
    cudaGetSymbolAddress((void**)&wq, g_wq);
    cudaGetSymbolAddress((void**)&wk, g_wk);
    cudaGetSymbolAddress((void**)&wv, g_wv);
    cudaGetSymbolAddress((void**)&idx, g_idx);
    cudaGetSymbolAddress((void**)&nk, g_nkeep);

    static int smem_set = 0;
    if (!smem_set) {
        cudaFuncSetAttribute(attention_kernel, cudaFuncAttributeMaxDynamicSharedMemorySize,
                             (32 * 512 + 64 * 65 + 32 * 65) * 4);
        smem_set = 1;
    }

    // 1. skipper
    skipper_scan<<<BB, SS>>>(keepm, idx, nk);
    gather_kernel<<<MTOT, 128>>>(x, idx, nk, xc);

    // 2. pack QKV weights
    pack_w<<<(DM * DM) / 256, 256>>>(w_qs, wq);
    pack_w<<<(DM * DM) / 256, 256>>>(w_ks, wk);
    pack_w<<<(DM * DM) / 256, 256>>>(w_vs, wv);

    // 3. QKV projections: [16384,512] @ [512,512]
    dim3 gproj(DM / 128, MTOT / 128);
    sgemm_kernel<<<gproj, 256>>>(xc, wq, q, MTOT, DM, DM, nullptr, 0);
    sgemm_kernel<<<gproj, 256>>>(xc, wk, k, MTOT, DM, DM, nullptr, 0);
    sgemm_kernel<<<gproj, 256>>>(xc, wv, v, MTOT, DM, DM, nullptr, 0);

    // 4. fused attention (writes attns + heads)
    dim3 gatt(BB * NH, SS / 32);
    attention_kernel<<<gatt, 256, (32 * 512 + 64 * 65 + 32 * 65) * 4>>>(q, k, v, nk, attns, heads);

    // 5. output projection + LN1
    sgemm_kernel<<<gproj, 256>>>(heads, proj_w, tmp, MTOT, DM, DM, proj_b, 0);
    ln_kernel<<<MTOT, 128>>>(tmp, xc, ln1_g, ln1_b, attn_out);

    // 6. FFN
    dim3 gff1(DINNER / 128, MTOT / 128);
    sgemm_kernel<<<gff1, 256>>>(attn_out, ffn_w1, ffnh, MTOT, DINNER, DM, ffn_b1, 1);
    sgemm_kernel<<<gproj, 256>>>(ffnh, ffn_w2, tmp, MTOT, DM, DINNER, ffn_b2, 0);
    ln_kernel<<<MTOT, 128>>>(tmp, attn_out, ln2_g, ln2_b, enc_out);
}